// round 11
// baseline (speedup 1.0000x reference)
#include <cuda_runtime.h>
#include <cuda_fp16.h>
#include <cuda_bf16.h>
#include <cstdint>
#include <cstddef>

#define N_SRC   100000
#define N_OUT   100000
#define N_EDGES 1600000
#define C       128

// ---------------- scratch (device globals; no allocation allowed) ------------
__device__ __half        g_Wxh[(size_t)N_SRC * C];  // node-major fp16 Wx
__device__ __half        g_numh[(size_t)N_OUT * C]; // fp16 accumulators
__device__ float         g_expa[N_SRC];
__device__ float         g_den[N_OUT];
__device__ __nv_bfloat16 g_Whi[C * C];              // W bf16 hi, row-major [o][k]
__device__ __nv_bfloat16 g_Wlo[C * C];              // W bf16 lo

// ---------------- kernel 0: one-time W split to bf16 hi/lo -------------------
__global__ void wcvt_kernel(const float* __restrict__ W)
{
    const int i = blockIdx.x * 256 + threadIdx.x;
    const float f = W[i];
    const __nv_bfloat16 hb = __float2bfloat16(f);
    g_Whi[i] = hb;
    g_Wlo[i] = __float2bfloat16(f - __bfloat162float(hb));
}

// ---------------- tensor-core GEMM helpers -----------------------------------
#define LDSM_X4(r0, r1, r2, r3, addr)                                          \
    asm volatile("ldmatrix.sync.aligned.m8n8.x4.shared.b16 {%0,%1,%2,%3},[%4];"\
                 : "=r"(r0), "=r"(r1), "=r"(r2), "=r"(r3) : "r"(addr))

#define LDSM_X4_T(r0, r1, r2, r3, addr)                                        \
    asm volatile("ldmatrix.sync.aligned.m8n8.x4.trans.shared.b16 {%0,%1,%2,%3},[%4];"\
                 : "=r"(r0), "=r"(r1), "=r"(r2), "=r"(r3) : "r"(addr))

#define MMA_BF16(c, a0, a1, a2, a3, b0, b1)                                    \
    asm volatile("mma.sync.aligned.m16n8k16.row.col.f32.bf16.bf16.f32 "        \
                 "{%0,%1,%2,%3},{%4,%5,%6,%7},{%8,%9},{%0,%1,%2,%3};"          \
                 : "+f"(c[0]), "+f"(c[1]), "+f"(c[2]), "+f"(c[3])              \
                 : "r"(a0), "r"(a1), "r"(a2), "r"(a3), "r"(b0), "r"(b1))

#define CP_ASYNC16(dst, src, szb)                                              \
    asm volatile("cp.async.ca.shared.global [%0], [%1], 16, %2;"               \
                 :: "r"(dst), "l"(src), "r"(szb))
#define CP_COMMIT() asm volatile("cp.async.commit_group;")
#define CP_WAIT0()  asm volatile("cp.async.wait_group 0;")

__device__ __forceinline__ void cvt_hilo4(float4 v, unsigned& hi0, unsigned& hi1,
                                          unsigned& lo0, unsigned& lo1)
{
    float f[4] = {v.x, v.y, v.z, v.w};
    unsigned short h[4], l[4];
#pragma unroll
    for (int i = 0; i < 4; i++) {
        __nv_bfloat16 hb = __float2bfloat16(f[i]);
        __nv_bfloat16 lb = __float2bfloat16(f[i] - __bfloat162float(hb));
        h[i] = __bfloat16_as_ushort(hb);
        l[i] = __bfloat16_as_ushort(lb);
    }
    hi0 = ((unsigned)h[1] << 16) | h[0];
    hi1 = ((unsigned)h[3] << 16) | h[2];
    lo0 = ((unsigned)l[1] << 16) | l[0];
    lo1 = ((unsigned)l[3] << 16) | l[2];
}

// ---------------- kernel 1: Wx = W @ x + b via bf16-split mma.sync -----------
// K-step 16, cp.async one-step-ahead pipeline:
//   As (W) double-buffered bf16, straight cp.async from pre-split g_Whi/g_Wlo.
//   x fp32 cp.async into xraw stage (src-size zero-fill at N boundary), then
//   smem->smem convert to Bs hi/lo. Next step's loads issued before MMA block.
#define KCHUNK  16
#define A_PITCH 24    // 16 k + 8 pad (bf16)
#define B_PITCH 136   // 128 n + 8 pad (bf16)
#define NSTEPS  (C / KCHUNK)                  // 8
#define GEMM_BLOCKS ((N_SRC + 127) / 128)     // 782

// smem byte layout inside sbuf
#define AS_STRIDE 12288                       // one stage: hi(6144)+lo(6144)
#define OFF_AS    0                           // 2 stages: 24576
#define OFF_BSHI  24576                       // 16*136*2 = 4352
#define OFF_BSLO  28928                       // 4352
#define OFF_XRAW  33280                       // 16*128*4 = 8192
#define SBUF_SZ   41472                       // epilogue S (34816 B) aliases base

__global__ __launch_bounds__(256, 2) void gemm_kernel(
    const float* __restrict__ x,      // (C, N_SRC)
    const float* __restrict__ b,      // (C,)
    const float* __restrict__ att,    // (C,)
    const float* __restrict__ alphap) // scalar
{
    __shared__ __align__(16) unsigned char sbuf[SBUF_SZ];
    float*  xraw = reinterpret_cast<float*>(sbuf + OFF_XRAW);   // [16][128]
    __half* S    = reinterpret_cast<__half*>(sbuf);             // epilogue [128][136]
    __shared__ float bsh[128], ash[128], sdot[128];

    const int tid  = threadIdx.x;
    const int w    = tid >> 5;
    const int lane = tid & 31;
    const int nbase = blockIdx.x * 128;

    const unsigned sb = (unsigned)__cvta_generic_to_shared(sbuf);

    // ---- fused zeroing of numh/den ----
    {
        const unsigned gi  = blockIdx.x * 256 + tid;
        const unsigned gst = GEMM_BLOCKS * 256;
        uint4* np = reinterpret_cast<uint4*>(g_numh);
        const unsigned n8 = (unsigned)((size_t)N_OUT * C / 8);
        const uint4 z = make_uint4(0u, 0u, 0u, 0u);
        for (unsigned k = gi; k < n8; k += gst)
            np[k] = z;
        for (unsigned k = gi; k < N_OUT; k += gst)
            g_den[k] = 0.f;
    }

    if (tid < 128) { bsh[tid] = b[tid]; ash[tid] = att[tid]; sdot[tid] = 0.f; }
    const float alpha = __ldg(alphap);

    // ---- per-thread load mappings ----
    // W: thread -> (o = tid>>1, kq8 = (tid&1)*8); one 16B cp.async per hi/lo
    const int wo  = tid >> 1;
    const int wk8 = (tid & 1) * 8;
    // x: thread handles float4 indices tid and tid+256 over [16][32]
    const int xr0 = tid >> 5,         xc0 = (tid & 31) * 4;
    const int xr1 = (tid + 256) >> 5, xc1 = ((tid + 256) & 31) * 4;

    auto issue_step = [&](int s) {
        const int kbase = s * KCHUNK;
        const unsigned as = sb + OFF_AS + (s & 1) * AS_STRIDE;
        CP_ASYNC16(as + (unsigned)((wo * A_PITCH + wk8) * 2),
                   &g_Whi[wo * C + kbase + wk8], 16);
        CP_ASYNC16(as + 6144u + (unsigned)((wo * A_PITCH + wk8) * 2),
                   &g_Wlo[wo * C + kbase + wk8], 16);
        {
            int bn  = nbase + xc0;
            int szb = (N_SRC - bn) * 4; szb = szb < 0 ? 0 : (szb > 16 ? 16 : szb);
            const float* sp = x + (size_t)(kbase + xr0) * N_SRC + (bn < N_SRC - 4 ? bn : N_SRC - 4);
            CP_ASYNC16(sb + OFF_XRAW + (unsigned)((xr0 * 128 + xc0) * 4), sp, szb);
        }
        {
            int bn  = nbase + xc1;
            int szb = (N_SRC - bn) * 4; szb = szb < 0 ? 0 : (szb > 16 ? 16 : szb);
            const float* sp = x + (size_t)(kbase + xr1) * N_SRC + (bn < N_SRC - 4 ? bn : N_SRC - 4);
            CP_ASYNC16(sb + OFF_XRAW + (unsigned)((xr1 * 128 + xc1) * 4), sp, szb);
        }
        CP_COMMIT();
    };

    const int lrow  = lane & 15;
    const int lcol8 = (lane >> 4) * 8;

    const int ow = w & 1;        // o-half: 64 o
    const int nw = w >> 1;       // n-quarter: 32 n
    const int nb = nw * 32;
    const int ob = ow * 64;

    float cc[4][4][4];
#pragma unroll
    for (int mt = 0; mt < 4; mt++)
#pragma unroll
        for (int nt = 0; nt < 4; nt++)
#pragma unroll
            for (int j = 0; j < 4; j++) cc[mt][nt][j] = 0.f;

    issue_step(0);

    for (int s = 0; s < NSTEPS; s++) {
        CP_WAIT0();
        __syncthreads();   // loads landed; previous compute done (Bs free)

        // ---- convert xraw -> Bs hi/lo ----
#pragma unroll
        for (int h = 0; h < 2; h++) {
            const int r = h ? xr1 : xr0;
            const int c = h ? xc1 : xc0;
            float4 v = *reinterpret_cast<const float4*>(&xraw[r * 128 + c]);
            unsigned h0, h1, l0, l1;
            cvt_hilo4(v, h0, h1, l0, l1);
            unsigned* dh = reinterpret_cast<unsigned*>(sbuf + OFF_BSHI + (r * B_PITCH + c) * 2);
            unsigned* dl = reinterpret_cast<unsigned*>(sbuf + OFF_BSLO + (r * B_PITCH + c) * 2);
            dh[0] = h0; dh[1] = h1;
            dl[0] = l0; dl[1] = l1;
        }
        __syncthreads();

        if (s + 1 < NSTEPS) issue_step(s + 1);   // overlap next loads with MMA

        // ---- compute this k16 step ----
        const unsigned boff0 = sb + OFF_BSHI + (unsigned)((lrow * B_PITCH + nb + lcol8) * 2);
        const unsigned boff1 = sb + OFF_BSHI + (unsigned)((lrow * B_PITCH + nb + 16 + lcol8) * 2);
        const unsigned doff  = OFF_BSLO - OFF_BSHI;
        unsigned bh[8], bl[8];
        LDSM_X4_T(bh[0], bh[1], bh[2], bh[3], boff0);
        LDSM_X4_T(bh[4], bh[5], bh[6], bh[7], boff1);
        LDSM_X4_T(bl[0], bl[1], bl[2], bl[3], boff0 + doff);
        LDSM_X4_T(bl[4], bl[5], bl[6], bl[7], boff1 + doff);

        const unsigned as = sb + OFF_AS + (s & 1) * AS_STRIDE;
#pragma unroll
        for (int mt = 0; mt < 4; mt++) {
            const unsigned aoff = as + (unsigned)(((ob + mt * 16 + lrow) * A_PITCH + lcol8) * 2);
            unsigned ah0, ah1, ah2, ah3, al0, al1, al2, al3;
            LDSM_X4(ah0, ah1, ah2, ah3, aoff);
            LDSM_X4(al0, al1, al2, al3, aoff + 6144u);

#pragma unroll
            for (int nt = 0; nt < 4; nt++) {
                MMA_BF16(cc[mt][nt], ah0, ah1, ah2, ah3, bh[2*nt], bh[2*nt+1]);
                MMA_BF16(cc[mt][nt], ah0, ah1, ah2, ah3, bl[2*nt], bl[2*nt+1]);
                MMA_BF16(cc[mt][nt], al0, al1, al2, al3, bh[2*nt], bh[2*nt+1]);
            }
        }
    }

    __syncthreads();   // mainloop smem dead; S may alias it

    // ---- epilogue: bias, att-dot partials, fp16 staging ----
    const int g  = lane >> 2;
    const int tg = lane & 3;
    float part[4][2];
#pragma unroll
    for (int nt = 0; nt < 4; nt++) { part[nt][0] = 0.f; part[nt][1] = 0.f; }

#pragma unroll
    for (int mt = 0; mt < 4; mt++) {
        const int o0 = ob + mt * 16 + g;
        const int o1 = o0 + 8;
        const float b0 = bsh[o0], b1 = bsh[o1];
        const float a0 = ash[o0], a1 = ash[o1];
#pragma unroll
        for (int nt = 0; nt < 4; nt++) {
            const float c0 = cc[mt][nt][0] + b0;
            const float c1 = cc[mt][nt][1] + b0;
            const float c2 = cc[mt][nt][2] + b1;
            const float c3 = cc[mt][nt][3] + b1;
            const int n0 = nb + nt * 8 + tg * 2;
            S[n0 * B_PITCH + o0]       = __float2half(c0);
            S[(n0 + 1) * B_PITCH + o0] = __float2half(c1);
            S[n0 * B_PITCH + o1]       = __float2half(c2);
            S[(n0 + 1) * B_PITCH + o1] = __float2half(c3);
            part[nt][0] += a0 * c0 + a1 * c2;
            part[nt][1] += a0 * c1 + a1 * c3;
        }
    }

#pragma unroll
    for (int m = 4; m < 32; m <<= 1)
#pragma unroll
        for (int nt = 0; nt < 4; nt++)
#pragma unroll
            for (int j = 0; j < 2; j++)
                part[nt][j] += __shfl_xor_sync(0xFFFFFFFFu, part[nt][j], m);

    if (lane < 4) {
#pragma unroll
        for (int nt = 0; nt < 4; nt++)
#pragma unroll
            for (int j = 0; j < 2; j++)
                atomicAdd(&sdot[nb + nt * 8 + lane * 2 + j], part[nt][j]);
    }
    __syncthreads();

    if (tid < 128) {
        const int n = nbase + tid;
        if (n < N_SRC) {
            float a = sdot[tid];
            a = (a >= 0.f) ? a : alpha * a;
            g_expa[n] = __expf(a);
        }
    }

    for (int idx = tid; idx < 128 * 16; idx += 256) {
        const int n  = idx >> 4;
        const int c8 = (idx & 15) * 8;
        const int gn = nbase + n;
        if (gn < N_SRC)
            *reinterpret_cast<uint4*>(&g_Wxh[(size_t)gn * C + c8]) =
                *reinterpret_cast<const uint4*>(&S[n * B_PITCH + c8]);
    }
}

// ---------------- kernel 2: edge scatter (16 lanes/edge, fp16x2 v4 reds) -----
__global__ __launch_bounds__(256) void scatter_kernel(const int* __restrict__ edges)
{
    const int e = blockIdx.x * 16 + (threadIdx.x >> 4);
    const int l = threadIdx.x & 15;

    const int2 ts = reinterpret_cast<const int2*>(edges)[e];
    const int tgt = ts.x;
    const int src = ts.y;

    const float ex = __ldg((const float*)&g_expa[src]);

    const uint4 h = *reinterpret_cast<const uint4*>(&g_Wxh[(size_t)src * C + l * 8]);
    unsigned p[4];
    {
        const unsigned hv[4] = {h.x, h.y, h.z, h.w};
#pragma unroll
        for (int i = 0; i < 4; i++) {
            float2 f = __half22float2(*reinterpret_cast<const __half2*>(&hv[i]));
            __half2 r = __floats2half2_rn(f.x * ex, f.y * ex);
            p[i] = *reinterpret_cast<unsigned*>(&r);
        }
    }

    __half* np = &g_numh[(size_t)tgt * C + l * 8];
    asm volatile("red.global.add.noftz.v4.f16x2 [%0], {%1, %2, %3, %4};"
                 :: "l"(np), "r"(p[0]), "r"(p[1]), "r"(p[2]), "r"(p[3])
                 : "memory");

    if (l == 0)
        atomicAdd(&g_den[tgt], ex);
}

// ---------------- kernel 3: normalize + transpose, 32 n x 128 o per block ----
__global__ __launch_bounds__(256) void finalize_kernel(float* __restrict__ out)
{
    __shared__ float tile[32][129];
    __shared__ float dsh[32];

    const int tid  = threadIdx.x;
    const int lane = tid & 31;
    const int w    = tid >> 5;
    const int n0   = blockIdx.x * 32;

    if (tid < 32) {
        float d = g_den[n0 + tid];
        dsh[tid] = (d == 0.f) ? 1.f : d;
    }

#pragma unroll
    for (int it = 0; it < 2; it++) {
        const int idx = it * 256 + tid;
        const int n   = idx >> 4;
        const int o8  = (idx & 15) * 8;
        const uint4 hv =
            *reinterpret_cast<const uint4*>(&g_numh[(size_t)(n0 + n) * C + o8]);
        const unsigned hs[4] = {hv.x, hv.y, hv.z, hv.w};
#pragma unroll
        for (int i = 0; i < 4; i++) {
            const float2 f = __half22float2(*reinterpret_cast<const __half2*>(&hs[i]));
            tile[n][o8 + i * 2 + 0] = f.x;
            tile[n][o8 + i * 2 + 1] = f.y;
        }
    }
    __syncthreads();

    const float rd = 1.f / dsh[lane];
#pragma unroll
    for (int r = 0; r < 16; r++) {
        const int o = w + r * 8;
        out[(size_t)o * N_OUT + n0 + lane] = tile[lane][o] * rd;
    }
}

// ---------------- launch ------------------------------------------------------
extern "C" void kernel_launch(void* const* d_in, const int* in_sizes, int n_in,
                              void* d_out, int out_size)
{
    const float* x     = (const float*)d_in[0];
    const int*   edges = (const int*)  d_in[1];
    const float* W     = (const float*)d_in[2];
    const float* b     = (const float*)d_in[3];
    const float* att   = (const float*)d_in[4];
    const float* alpha = (const float*)d_in[5];
    float* out = (float*)d_out;

    wcvt_kernel<<<64, 256>>>(W);
    gemm_kernel<<<GEMM_BLOCKS, 256>>>(x, b, att, alpha);
    scatter_kernel<<<N_EDGES / 16, 256>>>(edges);
    finalize_kernel<<<N_OUT / 32, 256>>>(out);
}

// round 12
// speedup vs baseline: 1.1297x; 1.1297x over previous
#include <cuda_runtime.h>
#include <cuda_fp16.h>
#include <cuda_bf16.h>
#include <cstdint>
#include <cstddef>

#define N_SRC   100000
#define N_OUT   100000
#define N_EDGES 1600000
#define C       128

// ---------------- scratch (device globals; no allocation allowed) ------------
__device__ __half        g_Wxh[(size_t)N_SRC * C];  // node-major fp16 Wx
__device__ __half        g_numh[(size_t)N_OUT * C]; // fp16 accumulators
__device__ float         g_expa[N_SRC];
__device__ float         g_den[N_OUT];
__device__ __nv_bfloat16 g_Whi[C * C];              // W bf16 hi, row-major [o][k]
__device__ __nv_bfloat16 g_Wlo[C * C];              // W bf16 lo

// ---------------- kernel 0: one-time W split to bf16 hi/lo -------------------
__global__ void wcvt_kernel(const float* __restrict__ W)
{
    const int i = blockIdx.x * 256 + threadIdx.x;
    const float f = W[i];
    const __nv_bfloat16 hb = __float2bfloat16(f);
    g_Whi[i] = hb;
    g_Wlo[i] = __float2bfloat16(f - __bfloat162float(hb));
}

// ---------------- tensor-core GEMM helpers -----------------------------------
#define LDSM_X4(r0, r1, r2, r3, addr)                                          \
    asm volatile("ldmatrix.sync.aligned.m8n8.x4.shared.b16 {%0,%1,%2,%3},[%4];"\
                 : "=r"(r0), "=r"(r1), "=r"(r2), "=r"(r3) : "r"(addr))

#define LDSM_X4_T(r0, r1, r2, r3, addr)                                        \
    asm volatile("ldmatrix.sync.aligned.m8n8.x4.trans.shared.b16 {%0,%1,%2,%3},[%4];"\
                 : "=r"(r0), "=r"(r1), "=r"(r2), "=r"(r3) : "r"(addr))

#define MMA_BF16(c, a0, a1, a2, a3, b0, b1)                                    \
    asm volatile("mma.sync.aligned.m16n8k16.row.col.f32.bf16.bf16.f32 "        \
                 "{%0,%1,%2,%3},{%4,%5,%6,%7},{%8,%9},{%0,%1,%2,%3};"          \
                 : "+f"(c[0]), "+f"(c[1]), "+f"(c[2]), "+f"(c[3])              \
                 : "r"(a0), "r"(a1), "r"(a2), "r"(a3), "r"(b0), "r"(b1))

__device__ __forceinline__ void cvt_hilo4(float4 v, unsigned& hi0, unsigned& hi1,
                                          unsigned& lo0, unsigned& lo1)
{
    float f[4] = {v.x, v.y, v.z, v.w};
    unsigned short h[4], l[4];
#pragma unroll
    for (int i = 0; i < 4; i++) {
        __nv_bfloat16 hb = __float2bfloat16(f[i]);
        __nv_bfloat16 lb = __float2bfloat16(f[i] - __bfloat162float(hb));
        h[i] = __bfloat16_as_ushort(hb);
        l[i] = __bfloat16_as_ushort(lb);
    }
    hi0 = ((unsigned)h[1] << 16) | h[0];
    hi1 = ((unsigned)h[3] << 16) | h[2];
    lo0 = ((unsigned)l[1] << 16) | l[0];
    lo1 = ((unsigned)l[3] << 16) | l[2];
}

// ---------------- kernel 1: Wx = W @ x + b via bf16-split mma.sync -----------
// (proven R10 version: K chunks of 32, warp tile 32n x 64o)
#define A_PITCH 40    // 32 k + 8 pad (bf16)
#define B_PITCH 136   // 128 n + 8 pad (bf16)
#define GEMM_BLOCKS ((N_SRC + 127) / 128)     // 782

__global__ __launch_bounds__(256, 2) void gemm_kernel(
    const float* __restrict__ x,      // (C, N_SRC)
    const float* __restrict__ b,      // (C,)
    const float* __restrict__ att,    // (C,)
    const float* __restrict__ alphap) // scalar
{
    __shared__ __align__(16) unsigned char sbuf[37888];
    __nv_bfloat16* As_hi = reinterpret_cast<__nv_bfloat16*>(sbuf);          // [128][40]
    __nv_bfloat16* As_lo = reinterpret_cast<__nv_bfloat16*>(sbuf + 10240);
    __nv_bfloat16* Bs_hi = reinterpret_cast<__nv_bfloat16*>(sbuf + 20480);  // [32][136]
    __nv_bfloat16* Bs_lo = reinterpret_cast<__nv_bfloat16*>(sbuf + 29184);
    __half*        S     = reinterpret_cast<__half*>(sbuf);                 // epilogue [128][136]
    __shared__ float bsh[128], ash[128], sdot[128];

    const int tid  = threadIdx.x;
    const int w    = tid >> 5;
    const int lane = tid & 31;
    const int nbase = blockIdx.x * 128;

    // ---- fused zeroing of numh/den ----
    {
        const unsigned gi  = blockIdx.x * 256 + tid;
        const unsigned gst = GEMM_BLOCKS * 256;
        uint4* np = reinterpret_cast<uint4*>(g_numh);
        const unsigned n8 = (unsigned)((size_t)N_OUT * C / 8);
        const uint4 z = make_uint4(0u, 0u, 0u, 0u);
        for (unsigned k = gi; k < n8; k += gst)
            np[k] = z;
        for (unsigned k = gi; k < N_OUT; k += gst)
            g_den[k] = 0.f;
    }

    if (tid < 128) { bsh[tid] = b[tid]; ash[tid] = att[tid]; sdot[tid] = 0.f; }
    const float alpha = __ldg(alphap);

    const unsigned saAhi = (unsigned)__cvta_generic_to_shared(As_hi);
    const unsigned saAlo = (unsigned)__cvta_generic_to_shared(As_lo);
    const unsigned saBhi = (unsigned)__cvta_generic_to_shared(Bs_hi);
    const unsigned saBlo = (unsigned)__cvta_generic_to_shared(Bs_lo);

    const int lrow  = lane & 15;
    const int lcol8 = (lane >> 4) * 8;

    const int ow = w & 1;        // o-half: 64 o
    const int nw = w >> 1;       // n-quarter: 32 n
    const int nb = nw * 32;
    const int ob = ow * 64;

    float cc[4][4][4];
#pragma unroll
    for (int mt = 0; mt < 4; mt++)
#pragma unroll
        for (int nt = 0; nt < 4; nt++)
#pragma unroll
            for (int j = 0; j < 4; j++) cc[mt][nt][j] = 0.f;

    for (int kc = 0; kc < 4; kc++) {
        const int kbase = kc * 32;
        __syncthreads();

#pragma unroll
        for (int it = 0; it < 2; it++) {
            const int idx = it * 256 + tid;
            const int o   = idx >> 2;
            const int kq  = (idx & 3) * 8;
            *reinterpret_cast<uint4*>(&As_hi[o * A_PITCH + kq]) =
                *reinterpret_cast<const uint4*>(&g_Whi[o * C + kbase + kq]);
            *reinterpret_cast<uint4*>(&As_lo[o * A_PITCH + kq]) =
                *reinterpret_cast<const uint4*>(&g_Wlo[o * C + kbase + kq]);
        }

#pragma unroll
        for (int it = 0; it < 4; it++) {
            const int r = it * 8 + w;
            const int n = nbase + lane * 4;
            float4 v = make_float4(0.f, 0.f, 0.f, 0.f);
            if (n < N_SRC)
                v = *reinterpret_cast<const float4*>(&x[(size_t)(kbase + r) * N_SRC + n]);
            unsigned h0, h1, l0, l1;
            cvt_hilo4(v, h0, h1, l0, l1);
            unsigned* dh = reinterpret_cast<unsigned*>(&Bs_hi[r * B_PITCH + lane * 4]);
            unsigned* dl = reinterpret_cast<unsigned*>(&Bs_lo[r * B_PITCH + lane * 4]);
            dh[0] = h0; dh[1] = h1;
            dl[0] = l0; dl[1] = l1;
        }
        __syncthreads();

#pragma unroll
        for (int ks = 0; ks < 2; ks++) {
            const int ko = ks * 16;
            const unsigned boff0 = (unsigned)(((ko + lrow) * B_PITCH + nb + lcol8) * 2);
            const unsigned boff1 = (unsigned)(((ko + lrow) * B_PITCH + nb + 16 + lcol8) * 2);
            unsigned bh[8], bl[8];
            LDSM_X4_T(bh[0], bh[1], bh[2], bh[3], saBhi + boff0);
            LDSM_X4_T(bh[4], bh[5], bh[6], bh[7], saBhi + boff1);
            LDSM_X4_T(bl[0], bl[1], bl[2], bl[3], saBlo + boff0);
            LDSM_X4_T(bl[4], bl[5], bl[6], bl[7], saBlo + boff1);

#pragma unroll
            for (int mt = 0; mt < 4; mt++) {
                const unsigned aoff =
                    (unsigned)(((ob + mt * 16 + lrow) * A_PITCH + ko + lcol8) * 2);
                unsigned ah0, ah1, ah2, ah3, al0, al1, al2, al3;
                LDSM_X4(ah0, ah1, ah2, ah3, saAhi + aoff);
                LDSM_X4(al0, al1, al2, al3, saAlo + aoff);

#pragma unroll
                for (int nt = 0; nt < 4; nt++) {
                    MMA_BF16(cc[mt][nt], ah0, ah1, ah2, ah3, bh[2*nt], bh[2*nt+1]);
                    MMA_BF16(cc[mt][nt], ah0, ah1, ah2, ah3, bl[2*nt], bl[2*nt+1]);
                    MMA_BF16(cc[mt][nt], al0, al1, al2, al3, bh[2*nt], bh[2*nt+1]);
                }
            }
        }
    }

    __syncthreads();   // mainloop smem dead; S may alias it

    // ---- epilogue: bias, att-dot partials, fp16 staging ----
    const int g  = lane >> 2;
    const int tg = lane & 3;
    float part[4][2];
#pragma unroll
    for (int nt = 0; nt < 4; nt++) { part[nt][0] = 0.f; part[nt][1] = 0.f; }

#pragma unroll
    for (int mt = 0; mt < 4; mt++) {
        const int o0 = ob + mt * 16 + g;
        const int o1 = o0 + 8;
        const float b0 = bsh[o0], b1 = bsh[o1];
        const float a0 = ash[o0], a1 = ash[o1];
#pragma unroll
        for (int nt = 0; nt < 4; nt++) {
            const float c0 = cc[mt][nt][0] + b0;
            const float c1 = cc[mt][nt][1] + b0;
            const float c2 = cc[mt][nt][2] + b1;
            const float c3 = cc[mt][nt][3] + b1;
            const int n0 = nb + nt * 8 + tg * 2;
            S[n0 * B_PITCH + o0]       = __float2half(c0);
            S[(n0 + 1) * B_PITCH + o0] = __float2half(c1);
            S[n0 * B_PITCH + o1]       = __float2half(c2);
            S[(n0 + 1) * B_PITCH + o1] = __float2half(c3);
            part[nt][0] += a0 * c0 + a1 * c2;
            part[nt][1] += a0 * c1 + a1 * c3;
        }
    }

#pragma unroll
    for (int m = 4; m < 32; m <<= 1)
#pragma unroll
        for (int nt = 0; nt < 4; nt++)
#pragma unroll
            for (int j = 0; j < 2; j++)
                part[nt][j] += __shfl_xor_sync(0xFFFFFFFFu, part[nt][j], m);

    if (lane < 4) {
#pragma unroll
        for (int nt = 0; nt < 4; nt++)
#pragma unroll
            for (int j = 0; j < 2; j++)
                atomicAdd(&sdot[nb + nt * 8 + lane * 2 + j], part[nt][j]);
    }
    __syncthreads();

    if (tid < 128) {
        const int n = nbase + tid;
        if (n < N_SRC) {
            float a = sdot[tid];
            a = (a >= 0.f) ? a : alpha * a;
            g_expa[n] = __expf(a);
        }
    }

    for (int idx = tid; idx < 128 * 16; idx += 256) {
        const int n  = idx >> 4;
        const int c8 = (idx & 15) * 8;
        const int gn = nbase + n;
        if (gn < N_SRC)
            *reinterpret_cast<uint4*>(&g_Wxh[(size_t)gn * C + c8]) =
                *reinterpret_cast<const uint4*>(&S[n * B_PITCH + c8]);
    }
}

// ---------------- kernel 2: edge scatter (2 edges per 16-lane group) ---------
// Edge pair loaded as one int4; two independent expa/row/red chains (MLP 2).
__global__ __launch_bounds__(256) void scatter_kernel(const int* __restrict__ edges)
{
    const int gidx = blockIdx.x * 16 + (threadIdx.x >> 4);   // pair index
    const int l    = threadIdx.x & 15;

    const int4 e2 = reinterpret_cast<const int4*>(edges)[gidx];  // edges 2g, 2g+1
    const int tgt0 = e2.x, src0 = e2.y;
    const int tgt1 = e2.z, src1 = e2.w;

    const float ex0 = __ldg(&g_expa[src0]);
    const float ex1 = __ldg(&g_expa[src1]);

    const uint4 h0 = *reinterpret_cast<const uint4*>(&g_Wxh[(size_t)src0 * C + l * 8]);
    const uint4 h1 = *reinterpret_cast<const uint4*>(&g_Wxh[(size_t)src1 * C + l * 8]);

    unsigned p0[4], p1[4];
    {
        const unsigned hv0[4] = {h0.x, h0.y, h0.z, h0.w};
        const unsigned hv1[4] = {h1.x, h1.y, h1.z, h1.w};
#pragma unroll
        for (int i = 0; i < 4; i++) {
            float2 f0 = __half22float2(*reinterpret_cast<const __half2*>(&hv0[i]));
            float2 f1 = __half22float2(*reinterpret_cast<const __half2*>(&hv1[i]));
            __half2 r0 = __floats2half2_rn(f0.x * ex0, f0.y * ex0);
            __half2 r1 = __floats2half2_rn(f1.x * ex1, f1.y * ex1);
            p0[i] = *reinterpret_cast<unsigned*>(&r0);
            p1[i] = *reinterpret_cast<unsigned*>(&r1);
        }
    }

    __half* np0 = &g_numh[(size_t)tgt0 * C + l * 8];
    __half* np1 = &g_numh[(size_t)tgt1 * C + l * 8];
    asm volatile("red.global.add.noftz.v4.f16x2 [%0], {%1, %2, %3, %4};"
                 :: "l"(np0), "r"(p0[0]), "r"(p0[1]), "r"(p0[2]), "r"(p0[3])
                 : "memory");
    asm volatile("red.global.add.noftz.v4.f16x2 [%0], {%1, %2, %3, %4};"
                 :: "l"(np1), "r"(p1[0]), "r"(p1[1]), "r"(p1[2]), "r"(p1[3])
                 : "memory");

    if (l == 0) {
        atomicAdd(&g_den[tgt0], ex0);
        atomicAdd(&g_den[tgt1], ex1);
    }
}

// ---------------- kernel 3: normalize + transpose, 32 n x 128 o per block ----
__global__ __launch_bounds__(256) void finalize_kernel(float* __restrict__ out)
{
    __shared__ float tile[32][129];
    __shared__ float dsh[32];

    const int tid  = threadIdx.x;
    const int lane = tid & 31;
    const int w    = tid >> 5;
    const int n0   = blockIdx.x * 32;

    if (tid < 32) {
        float d = g_den[n0 + tid];
        dsh[tid] = (d == 0.f) ? 1.f : d;
    }

#pragma unroll
    for (int it = 0; it < 2; it++) {
        const int idx = it * 256 + tid;
        const int n   = idx >> 4;
        const int o8  = (idx & 15) * 8;
        const uint4 hv =
            *reinterpret_cast<const uint4*>(&g_numh[(size_t)(n0 + n) * C + o8]);
        const unsigned hs[4] = {hv.x, hv.y, hv.z, hv.w};
#pragma unroll
        for (int i = 0; i < 4; i++) {
            const float2 f = __half22float2(*reinterpret_cast<const __half2*>(&hs[i]));
            tile[n][o8 + i * 2 + 0] = f.x;
            tile[n][o8 + i * 2 + 1] = f.y;
        }
    }
    __syncthreads();

    const float rd = 1.f / dsh[lane];
#pragma unroll
    for (int r = 0; r < 16; r++) {
        const int o = w + r * 8;
        out[(size_t)o * N_OUT + n0 + lane] = tile[lane][o] * rd;
    }
}

// ---------------- launch ------------------------------------------------------
extern "C" void kernel_launch(void* const* d_in, const int* in_sizes, int n_in,
                              void* d_out, int out_size)
{
    const float* x     = (const float*)d_in[0];
    const int*   edges = (const int*)  d_in[1];
    const float* W     = (const float*)d_in[2];
    const float* b     = (const float*)d_in[3];
    const float* att   = (const float*)d_in[4];
    const float* alpha = (const float*)d_in[5];
    float* out = (float*)d_out;

    wcvt_kernel<<<64, 256>>>(W);
    gemm_kernel<<<GEMM_BLOCKS, 256>>>(x, b, att, alpha);
    scatter_kernel<<<N_EDGES / 32, 256>>>(edges);
    finalize_kernel<<<N_OUT / 32, 256>>>(out);
}

// round 13
// speedup vs baseline: 1.1485x; 1.0167x over previous
#include <cuda_runtime.h>
#include <cuda_fp16.h>
#include <cuda_bf16.h>
#include <cstdint>
#include <cstddef>

#define N_SRC   100000
#define N_OUT   100000
#define N_EDGES 1600000
#define C       128

// ---------------- scratch (device globals; no allocation allowed) ------------
__device__ __half        g_Wxh[(size_t)N_SRC * C];  // node-major fp16 Wx
__device__ __half        g_numh[(size_t)N_OUT * C]; // fp16 accumulators
__device__ float         g_expa[N_SRC];
__device__ float         g_den[N_OUT];
__device__ __nv_bfloat16 g_Whi[C * C];              // W bf16 hi, row-major [o][k]
__device__ __nv_bfloat16 g_Wlo[C * C];              // W bf16 lo

// ---------------- kernel 0: one-time W split to bf16 hi/lo -------------------
__global__ void wcvt_kernel(const float* __restrict__ W)
{
    const int i = blockIdx.x * 256 + threadIdx.x;
    const float f = W[i];
    const __nv_bfloat16 hb = __float2bfloat16(f);
    g_Whi[i] = hb;
    g_Wlo[i] = __float2bfloat16(f - __bfloat162float(hb));
}

// ---------------- tensor-core GEMM helpers -----------------------------------
#define LDSM_X4(r0, r1, r2, r3, addr)                                          \
    asm volatile("ldmatrix.sync.aligned.m8n8.x4.shared.b16 {%0,%1,%2,%3},[%4];"\
                 : "=r"(r0), "=r"(r1), "=r"(r2), "=r"(r3) : "r"(addr))

#define LDSM_X4_T(r0, r1, r2, r3, addr)                                        \
    asm volatile("ldmatrix.sync.aligned.m8n8.x4.trans.shared.b16 {%0,%1,%2,%3},[%4];"\
                 : "=r"(r0), "=r"(r1), "=r"(r2), "=r"(r3) : "r"(addr))

#define MMA_BF16(c, a0, a1, a2, a3, b0, b1)                                    \
    asm volatile("mma.sync.aligned.m16n8k16.row.col.f32.bf16.bf16.f32 "        \
                 "{%0,%1,%2,%3},{%4,%5,%6,%7},{%8,%9},{%0,%1,%2,%3};"          \
                 : "+f"(c[0]), "+f"(c[1]), "+f"(c[2]), "+f"(c[3])              \
                 : "r"(a0), "r"(a1), "r"(a2), "r"(a3), "r"(b0), "r"(b1))

__device__ __forceinline__ void cvt_hilo4(float4 v, unsigned& hi0, unsigned& hi1,
                                          unsigned& lo0, unsigned& lo1)
{
    float f[4] = {v.x, v.y, v.z, v.w};
    unsigned short h[4], l[4];
#pragma unroll
    for (int i = 0; i < 4; i++) {
        __nv_bfloat16 hb = __float2bfloat16(f[i]);
        __nv_bfloat16 lb = __float2bfloat16(f[i] - __bfloat162float(hb));
        h[i] = __bfloat16_as_ushort(hb);
        l[i] = __bfloat16_as_ushort(lb);
    }
    hi0 = ((unsigned)h[1] << 16) | h[0];
    hi1 = ((unsigned)h[3] << 16) | h[2];
    lo0 = ((unsigned)l[1] << 16) | l[0];
    lo1 = ((unsigned)l[3] << 16) | l[2];
}

// ---------------- kernel 1: Wx = W @ x + b via bf16-split mma.sync -----------
// (proven R10/R12 version: K chunks of 32, warp tile 32n x 64o)
#define A_PITCH 40    // 32 k + 8 pad (bf16)
#define B_PITCH 136   // 128 n + 8 pad (bf16)
#define GEMM_BLOCKS ((N_SRC + 127) / 128)     // 782

__global__ __launch_bounds__(256, 2) void gemm_kernel(
    const float* __restrict__ x,      // (C, N_SRC)
    const float* __restrict__ b,      // (C,)
    const float* __restrict__ att,    // (C,)
    const float* __restrict__ alphap) // scalar
{
    __shared__ __align__(16) unsigned char sbuf[37888];
    __nv_bfloat16* As_hi = reinterpret_cast<__nv_bfloat16*>(sbuf);          // [128][40]
    __nv_bfloat16* As_lo = reinterpret_cast<__nv_bfloat16*>(sbuf + 10240);
    __nv_bfloat16* Bs_hi = reinterpret_cast<__nv_bfloat16*>(sbuf + 20480);  // [32][136]
    __nv_bfloat16* Bs_lo = reinterpret_cast<__nv_bfloat16*>(sbuf + 29184);
    __half*        S     = reinterpret_cast<__half*>(sbuf);                 // epilogue [128][136]
    __shared__ float bsh[128], ash[128], sdot[128];

    const int tid  = threadIdx.x;
    const int w    = tid >> 5;
    const int lane = tid & 31;
    const int nbase = blockIdx.x * 128;

    // ---- fused zeroing of numh/den ----
    {
        const unsigned gi  = blockIdx.x * 256 + tid;
        const unsigned gst = GEMM_BLOCKS * 256;
        uint4* np = reinterpret_cast<uint4*>(g_numh);
        const unsigned n8 = (unsigned)((size_t)N_OUT * C / 8);
        const uint4 z = make_uint4(0u, 0u, 0u, 0u);
        for (unsigned k = gi; k < n8; k += gst)
            np[k] = z;
        for (unsigned k = gi; k < N_OUT; k += gst)
            g_den[k] = 0.f;
    }

    if (tid < 128) { bsh[tid] = b[tid]; ash[tid] = att[tid]; sdot[tid] = 0.f; }
    const float alpha = __ldg(alphap);

    const unsigned saAhi = (unsigned)__cvta_generic_to_shared(As_hi);
    const unsigned saAlo = (unsigned)__cvta_generic_to_shared(As_lo);
    const unsigned saBhi = (unsigned)__cvta_generic_to_shared(Bs_hi);
    const unsigned saBlo = (unsigned)__cvta_generic_to_shared(Bs_lo);

    const int lrow  = lane & 15;
    const int lcol8 = (lane >> 4) * 8;

    const int ow = w & 1;        // o-half: 64 o
    const int nw = w >> 1;       // n-quarter: 32 n
    const int nb = nw * 32;
    const int ob = ow * 64;

    float cc[4][4][4];
#pragma unroll
    for (int mt = 0; mt < 4; mt++)
#pragma unroll
        for (int nt = 0; nt < 4; nt++)
#pragma unroll
            for (int j = 0; j < 4; j++) cc[mt][nt][j] = 0.f;

    for (int kc = 0; kc < 4; kc++) {
        const int kbase = kc * 32;
        __syncthreads();

#pragma unroll
        for (int it = 0; it < 2; it++) {
            const int idx = it * 256 + tid;
            const int o   = idx >> 2;
            const int kq  = (idx & 3) * 8;
            *reinterpret_cast<uint4*>(&As_hi[o * A_PITCH + kq]) =
                *reinterpret_cast<const uint4*>(&g_Whi[o * C + kbase + kq]);
            *reinterpret_cast<uint4*>(&As_lo[o * A_PITCH + kq]) =
                *reinterpret_cast<const uint4*>(&g_Wlo[o * C + kbase + kq]);
        }

#pragma unroll
        for (int it = 0; it < 4; it++) {
            const int r = it * 8 + w;
            const int n = nbase + lane * 4;
            float4 v = make_float4(0.f, 0.f, 0.f, 0.f);
            if (n < N_SRC)
                v = *reinterpret_cast<const float4*>(&x[(size_t)(kbase + r) * N_SRC + n]);
            unsigned h0, h1, l0, l1;
            cvt_hilo4(v, h0, h1, l0, l1);
            unsigned* dh = reinterpret_cast<unsigned*>(&Bs_hi[r * B_PITCH + lane * 4]);
            unsigned* dl = reinterpret_cast<unsigned*>(&Bs_lo[r * B_PITCH + lane * 4]);
            dh[0] = h0; dh[1] = h1;
            dl[0] = l0; dl[1] = l1;
        }
        __syncthreads();

#pragma unroll
        for (int ks = 0; ks < 2; ks++) {
            const int ko = ks * 16;
            const unsigned boff0 = (unsigned)(((ko + lrow) * B_PITCH + nb + lcol8) * 2);
            const unsigned boff1 = (unsigned)(((ko + lrow) * B_PITCH + nb + 16 + lcol8) * 2);
            unsigned bh[8], bl[8];
            LDSM_X4_T(bh[0], bh[1], bh[2], bh[3], saBhi + boff0);
            LDSM_X4_T(bh[4], bh[5], bh[6], bh[7], saBhi + boff1);
            LDSM_X4_T(bl[0], bl[1], bl[2], bl[3], saBlo + boff0);
            LDSM_X4_T(bl[4], bl[5], bl[6], bl[7], saBlo + boff1);

#pragma unroll
            for (int mt = 0; mt < 4; mt++) {
                const unsigned aoff =
                    (unsigned)(((ob + mt * 16 + lrow) * A_PITCH + ko + lcol8) * 2);
                unsigned ah0, ah1, ah2, ah3, al0, al1, al2, al3;
                LDSM_X4(ah0, ah1, ah2, ah3, saAhi + aoff);
                LDSM_X4(al0, al1, al2, al3, saAlo + aoff);

#pragma unroll
                for (int nt = 0; nt < 4; nt++) {
                    MMA_BF16(cc[mt][nt], ah0, ah1, ah2, ah3, bh[2*nt], bh[2*nt+1]);
                    MMA_BF16(cc[mt][nt], ah0, ah1, ah2, ah3, bl[2*nt], bl[2*nt+1]);
                    MMA_BF16(cc[mt][nt], al0, al1, al2, al3, bh[2*nt], bh[2*nt+1]);
                }
            }
        }
    }

    __syncthreads();   // mainloop smem dead; S may alias it

    // ---- epilogue: bias, att-dot partials, fp16 staging ----
    const int g  = lane >> 2;
    const int tg = lane & 3;
    float part[4][2];
#pragma unroll
    for (int nt = 0; nt < 4; nt++) { part[nt][0] = 0.f; part[nt][1] = 0.f; }

#pragma unroll
    for (int mt = 0; mt < 4; mt++) {
        const int o0 = ob + mt * 16 + g;
        const int o1 = o0 + 8;
        const float b0 = bsh[o0], b1 = bsh[o1];
        const float a0 = ash[o0], a1 = ash[o1];
#pragma unroll
        for (int nt = 0; nt < 4; nt++) {
            const float c0 = cc[mt][nt][0] + b0;
            const float c1 = cc[mt][nt][1] + b0;
            const float c2 = cc[mt][nt][2] + b1;
            const float c3 = cc[mt][nt][3] + b1;
            const int n0 = nb + nt * 8 + tg * 2;
            S[n0 * B_PITCH + o0]       = __float2half(c0);
            S[(n0 + 1) * B_PITCH + o0] = __float2half(c1);
            S[n0 * B_PITCH + o1]       = __float2half(c2);
            S[(n0 + 1) * B_PITCH + o1] = __float2half(c3);
            part[nt][0] += a0 * c0 + a1 * c2;
            part[nt][1] += a0 * c1 + a1 * c3;
        }
    }

#pragma unroll
    for (int m = 4; m < 32; m <<= 1)
#pragma unroll
        for (int nt = 0; nt < 4; nt++)
#pragma unroll
            for (int j = 0; j < 2; j++)
                part[nt][j] += __shfl_xor_sync(0xFFFFFFFFu, part[nt][j], m);

    if (lane < 4) {
#pragma unroll
        for (int nt = 0; nt < 4; nt++)
#pragma unroll
            for (int j = 0; j < 2; j++)
                atomicAdd(&sdot[nb + nt * 8 + lane * 2 + j], part[nt][j]);
    }
    __syncthreads();

    if (tid < 128) {
        const int n = nbase + tid;
        if (n < N_SRC) {
            float a = sdot[tid];
            a = (a >= 0.f) ? a : alpha * a;
            g_expa[n] = __expf(a);
        }
    }

    for (int idx = tid; idx < 128 * 16; idx += 256) {
        const int n  = idx >> 4;
        const int c8 = (idx & 15) * 8;
        const int gn = nbase + n;
        if (gn < N_SRC)
            *reinterpret_cast<uint4*>(&g_Wxh[(size_t)gn * C + c8]) =
                *reinterpret_cast<const uint4*>(&S[n * B_PITCH + c8]);
    }
}

// ---------------- kernel 2: edge scatter (4 edges per 16-lane group) ---------
// Four independent expa/row/red chains per thread (MLP 4).
__global__ __launch_bounds__(256) void scatter_kernel(const int* __restrict__ edges)
{
    const int gidx = blockIdx.x * 16 + (threadIdx.x >> 4);   // quad index
    const int l    = threadIdx.x & 15;

    const int4 ea = reinterpret_cast<const int4*>(edges)[gidx * 2];      // edges 4g, 4g+1
    const int4 eb = reinterpret_cast<const int4*>(edges)[gidx * 2 + 1];  // edges 4g+2, 4g+3

    const int tgt[4] = {ea.x, ea.z, eb.x, eb.z};
    const int src[4] = {ea.y, ea.w, eb.y, eb.w};

    float ex[4];
#pragma unroll
    for (int q = 0; q < 4; q++) ex[q] = __ldg(&g_expa[src[q]]);

    uint4 h[4];
#pragma unroll
    for (int q = 0; q < 4; q++)
        h[q] = *reinterpret_cast<const uint4*>(&g_Wxh[(size_t)src[q] * C + l * 8]);

#pragma unroll
    for (int q = 0; q < 4; q++) {
        const unsigned hv[4] = {h[q].x, h[q].y, h[q].z, h[q].w};
        unsigned p[4];
#pragma unroll
        for (int i = 0; i < 4; i++) {
            float2 f = __half22float2(*reinterpret_cast<const __half2*>(&hv[i]));
            __half2 r = __floats2half2_rn(f.x * ex[q], f.y * ex[q]);
            p[i] = *reinterpret_cast<unsigned*>(&r);
        }
        __half* np = &g_numh[(size_t)tgt[q] * C + l * 8];
        asm volatile("red.global.add.noftz.v4.f16x2 [%0], {%1, %2, %3, %4};"
                     :: "l"(np), "r"(p[0]), "r"(p[1]), "r"(p[2]), "r"(p[3])
                     : "memory");
    }

    if (l == 0) {
#pragma unroll
        for (int q = 0; q < 4; q++)
            atomicAdd(&g_den[tgt[q]], ex[q]);
    }
}

// ---------------- kernel 3: normalize + transpose, 32 n x 128 o per block ----
__global__ __launch_bounds__(256) void finalize_kernel(float* __restrict__ out)
{
    __shared__ float tile[32][129];
    __shared__ float dsh[32];

    const int tid  = threadIdx.x;
    const int lane = tid & 31;
    const int w    = tid >> 5;
    const int n0   = blockIdx.x * 32;

    if (tid < 32) {
        float d = g_den[n0 + tid];
        dsh[tid] = (d == 0.f) ? 1.f : d;
    }

#pragma unroll
    for (int it = 0; it < 2; it++) {
        const int idx = it * 256 + tid;
        const int n   = idx >> 4;
        const int o8  = (idx & 15) * 8;
        const uint4 hv =
            *reinterpret_cast<const uint4*>(&g_numh[(size_t)(n0 + n) * C + o8]);
        const unsigned hs[4] = {hv.x, hv.y, hv.z, hv.w};
#pragma unroll
        for (int i = 0; i < 4; i++) {
            const float2 f = __half22float2(*reinterpret_cast<const __half2*>(&hs[i]));
            tile[n][o8 + i * 2 + 0] = f.x;
            tile[n][o8 + i * 2 + 1] = f.y;
        }
    }
    __syncthreads();

    const float rd = 1.f / dsh[lane];
#pragma unroll
    for (int r = 0; r < 16; r++) {
        const int o = w + r * 8;
        out[(size_t)o * N_OUT + n0 + lane] = tile[lane][o] * rd;
    }
}

// ---------------- launch ------------------------------------------------------
extern "C" void kernel_launch(void* const* d_in, const int* in_sizes, int n_in,
                              void* d_out, int out_size)
{
    const float* x     = (const float*)d_in[0];
    const int*   edges = (const int*)  d_in[1];
    const float* W     = (const float*)d_in[2];
    const float* b     = (const float*)d_in[3];
    const float* att   = (const float*)d_in[4];
    const float* alpha = (const float*)d_in[5];
    float* out = (float*)d_out;

    wcvt_kernel<<<64, 256>>>(W);
    gemm_kernel<<<GEMM_BLOCKS, 256>>>(x, b, att, alpha);
    scatter_kernel<<<N_EDGES / 64, 256>>>(edges);
    finalize_kernel<<<N_OUT / 32, 256>>>(out);
}

// round 14
// speedup vs baseline: 1.1964x; 1.0417x over previous
#include <cuda_runtime.h>
#include <cuda_fp16.h>
#include <cstdint>
#include <cstddef>

#define N_SRC   100000
#define N_OUT   100000
#define N_EDGES 1600000
#define C       128

// ---------------- scratch (device globals; no allocation allowed) ------------
__device__ __half g_Wxh[(size_t)N_SRC * C];  // node-major fp16 Wx
__device__ __half g_numh[(size_t)N_OUT * C]; // fp16 accumulators
__device__ float  g_expa[N_SRC];
__device__ float  g_den[N_OUT];
__device__ __half g_Whf[C * C];              // W fp16, row-major [o][k]

// ---------------- kernel 0: one-time W -> fp16 -------------------------------
__global__ void wcvt_kernel(const float* __restrict__ W)
{
    const int i = blockIdx.x * 256 + threadIdx.x;   // 0..16383
    g_Whf[i] = __float2half_rn(W[i]);
}

// ---------------- tensor-core GEMM helpers -----------------------------------
#define LDSM_X4(r0, r1, r2, r3, addr)                                          \
    asm volatile("ldmatrix.sync.aligned.m8n8.x4.shared.b16 {%0,%1,%2,%3},[%4];"\
                 : "=r"(r0), "=r"(r1), "=r"(r2), "=r"(r3) : "r"(addr))

#define LDSM_X4_T(r0, r1, r2, r3, addr)                                        \
    asm volatile("ldmatrix.sync.aligned.m8n8.x4.trans.shared.b16 {%0,%1,%2,%3},[%4];"\
                 : "=r"(r0), "=r"(r1), "=r"(r2), "=r"(r3) : "r"(addr))

#define MMA_F16(c, a0, a1, a2, a3, b0, b1)                                     \
    asm volatile("mma.sync.aligned.m16n8k16.row.col.f32.f16.f16.f32 "          \
                 "{%0,%1,%2,%3},{%4,%5,%6,%7},{%8,%9},{%0,%1,%2,%3};"          \
                 : "+f"(c[0]), "+f"(c[1]), "+f"(c[2]), "+f"(c[3])              \
                 : "r"(a0), "r"(a1), "r"(a2), "r"(a3), "r"(b0), "r"(b1))

// split 4 floats into fp16 hi/lo packed pairs
__device__ __forceinline__ void cvt_hilo4_f16(float4 v, unsigned& hi0, unsigned& hi1,
                                              unsigned& lo0, unsigned& lo1)
{
    float f[4] = {v.x, v.y, v.z, v.w};
    unsigned short h[4], l[4];
#pragma unroll
    for (int i = 0; i < 4; i++) {
        __half hb = __float2half_rn(f[i]);
        __half lb = __float2half_rn(f[i] - __half2float(hb));
        h[i] = __half_as_ushort(hb);
        l[i] = __half_as_ushort(lb);
    }
    hi0 = ((unsigned)h[1] << 16) | h[0];
    hi1 = ((unsigned)h[3] << 16) | h[2];
    lo0 = ((unsigned)l[1] << 16) | l[0];
    lo1 = ((unsigned)l[3] << 16) | l[2];
}

// ---------------- kernel 1: Wx = W @ x + b via 2-term fp16 mma.sync ----------
// Block 128 n x 128 o; warp grid 4(n) x 2(o): warp owns 32 n x 64 o.
// D = Whf*xhi + Whf*xlo  (exact x reconstruction; only W carries fp16 rounding)
#define A_PITCH 40    // 32 k + 8 pad (fp16)
#define B_PITCH 136   // 128 n + 8 pad (fp16)
#define GEMM_BLOCKS ((N_SRC + 127) / 128)     // 782

// smem layout: As 10240 | Bs_hi 8704 | Bs_lo 8704 ; epilogue S (34816) aliases all
#define OFF_AS   0
#define OFF_BSHI 10240
#define OFF_BSLO 18944
#define SBUF_SZ  34816

__global__ __launch_bounds__(256, 2) void gemm_kernel(
    const float* __restrict__ x,      // (C, N_SRC)
    const float* __restrict__ b,      // (C,)
    const float* __restrict__ att,    // (C,)
    const float* __restrict__ alphap) // scalar
{
    __shared__ __align__(16) unsigned char sbuf[SBUF_SZ];
    __half* As    = reinterpret_cast<__half*>(sbuf + OFF_AS);     // [128][40]
    __half* Bs_hi = reinterpret_cast<__half*>(sbuf + OFF_BSHI);   // [32][136]
    __half* Bs_lo = reinterpret_cast<__half*>(sbuf + OFF_BSLO);
    __half* S     = reinterpret_cast<__half*>(sbuf);              // epilogue [128][136]
    __shared__ float bsh[128], ash[128], sdot[128];

    const int tid  = threadIdx.x;
    const int w    = tid >> 5;
    const int lane = tid & 31;
    const int nbase = blockIdx.x * 128;

    // ---- fused zeroing of numh/den ----
    {
        const unsigned gi  = blockIdx.x * 256 + tid;
        const unsigned gst = GEMM_BLOCKS * 256;
        uint4* np = reinterpret_cast<uint4*>(g_numh);
        const unsigned n8 = (unsigned)((size_t)N_OUT * C / 8);
        const uint4 z = make_uint4(0u, 0u, 0u, 0u);
        for (unsigned k = gi; k < n8; k += gst)
            np[k] = z;
        for (unsigned k = gi; k < N_OUT; k += gst)
            g_den[k] = 0.f;
    }

    if (tid < 128) { bsh[tid] = b[tid]; ash[tid] = att[tid]; sdot[tid] = 0.f; }
    const float alpha = __ldg(alphap);

    const unsigned saA   = (unsigned)__cvta_generic_to_shared(As);
    const unsigned saBhi = (unsigned)__cvta_generic_to_shared(Bs_hi);
    const unsigned saBlo = (unsigned)__cvta_generic_to_shared(Bs_lo);

    const int lrow  = lane & 15;
    const int lcol8 = (lane >> 4) * 8;

    const int ow = w & 1;        // o-half: 64 o
    const int nw = w >> 1;       // n-quarter: 32 n
    const int nb = nw * 32;
    const int ob = ow * 64;

    float cc[4][4][4];
#pragma unroll
    for (int mt = 0; mt < 4; mt++)
#pragma unroll
        for (int nt = 0; nt < 4; nt++)
#pragma unroll
            for (int j = 0; j < 4; j++) cc[mt][nt][j] = 0.f;

    for (int kc = 0; kc < 4; kc++) {
        const int kbase = kc * 32;
        __syncthreads();

        // ---- W chunk: straight fp16 copy gmem -> smem ----
#pragma unroll
        for (int it = 0; it < 2; it++) {
            const int idx = it * 256 + tid;       // 0..511 uint4s
            const int o   = idx >> 2;
            const int kq  = (idx & 3) * 8;
            *reinterpret_cast<uint4*>(&As[o * A_PITCH + kq]) =
                *reinterpret_cast<const uint4*>(&g_Whf[o * C + kbase + kq]);
        }

        // ---- x chunk: load fp32, split to fp16 hi/lo ----
#pragma unroll
        for (int it = 0; it < 4; it++) {
            const int r = it * 8 + w;
            const int n = nbase + lane * 4;
            float4 v = make_float4(0.f, 0.f, 0.f, 0.f);
            if (n < N_SRC)
                v = *reinterpret_cast<const float4*>(&x[(size_t)(kbase + r) * N_SRC + n]);
            unsigned h0, h1, l0, l1;
            cvt_hilo4_f16(v, h0, h1, l0, l1);
            unsigned* dh = reinterpret_cast<unsigned*>(&Bs_hi[r * B_PITCH + lane * 4]);
            unsigned* dl = reinterpret_cast<unsigned*>(&Bs_lo[r * B_PITCH + lane * 4]);
            dh[0] = h0; dh[1] = h1;
            dl[0] = l0; dl[1] = l1;
        }
        __syncthreads();

#pragma unroll
        for (int ks = 0; ks < 2; ks++) {
            const int ko = ks * 16;
            const unsigned boff0 = (unsigned)(((ko + lrow) * B_PITCH + nb + lcol8) * 2);
            const unsigned boff1 = (unsigned)(((ko + lrow) * B_PITCH + nb + 16 + lcol8) * 2);
            unsigned bh[8], bl[8];
            LDSM_X4_T(bh[0], bh[1], bh[2], bh[3], saBhi + boff0);
            LDSM_X4_T(bh[4], bh[5], bh[6], bh[7], saBhi + boff1);
            LDSM_X4_T(bl[0], bl[1], bl[2], bl[3], saBlo + boff0);
            LDSM_X4_T(bl[4], bl[5], bl[6], bl[7], saBlo + boff1);

#pragma unroll
            for (int mt = 0; mt < 4; mt++) {
                const unsigned aoff =
                    saA + (unsigned)(((ob + mt * 16 + lrow) * A_PITCH + ko + lcol8) * 2);
                unsigned a0, a1, a2, a3;
                LDSM_X4(a0, a1, a2, a3, aoff);

#pragma unroll
                for (int nt = 0; nt < 4; nt++) {
                    MMA_F16(cc[mt][nt], a0, a1, a2, a3, bh[2*nt], bh[2*nt+1]);
                    MMA_F16(cc[mt][nt], a0, a1, a2, a3, bl[2*nt], bl[2*nt+1]);
                }
            }
        }
    }

    __syncthreads();   // mainloop smem dead; S may alias it

    // ---- epilogue: bias, att-dot partials, fp16 staging ----
    const int g  = lane >> 2;
    const int tg = lane & 3;
    float part[4][2];
#pragma unroll
    for (int nt = 0; nt < 4; nt++) { part[nt][0] = 0.f; part[nt][1] = 0.f; }

#pragma unroll
    for (int mt = 0; mt < 4; mt++) {
        const int o0 = ob + mt * 16 + g;
        const int o1 = o0 + 8;
        const float b0 = bsh[o0], b1 = bsh[o1];
        const float a0 = ash[o0], a1 = ash[o1];
#pragma unroll
        for (int nt = 0; nt < 4; nt++) {
            const float c0 = cc[mt][nt][0] + b0;
            const float c1 = cc[mt][nt][1] + b0;
            const float c2 = cc[mt][nt][2] + b1;
            const float c3 = cc[mt][nt][3] + b1;
            const int n0 = nb + nt * 8 + tg * 2;
            S[n0 * B_PITCH + o0]       = __float2half(c0);
            S[(n0 + 1) * B_PITCH + o0] = __float2half(c1);
            S[n0 * B_PITCH + o1]       = __float2half(c2);
            S[(n0 + 1) * B_PITCH + o1] = __float2half(c3);
            part[nt][0] += a0 * c0 + a1 * c2;
            part[nt][1] += a0 * c1 + a1 * c3;
        }
    }

#pragma unroll
    for (int m = 4; m < 32; m <<= 1)
#pragma unroll
        for (int nt = 0; nt < 4; nt++)
#pragma unroll
            for (int j = 0; j < 2; j++)
                part[nt][j] += __shfl_xor_sync(0xFFFFFFFFu, part[nt][j], m);

    if (lane < 4) {
#pragma unroll
        for (int nt = 0; nt < 4; nt++)
#pragma unroll
            for (int j = 0; j < 2; j++)
                atomicAdd(&sdot[nb + nt * 8 + lane * 2 + j], part[nt][j]);
    }
    __syncthreads();

    if (tid < 128) {
        const int n = nbase + tid;
        if (n < N_SRC) {
            float a = sdot[tid];
            a = (a >= 0.f) ? a : alpha * a;
            g_expa[n] = __expf(a);
        }
    }

    for (int idx = tid; idx < 128 * 16; idx += 256) {
        const int n  = idx >> 4;
        const int c8 = (idx & 15) * 8;
        const int gn = nbase + n;
        if (gn < N_SRC)
            *reinterpret_cast<uint4*>(&g_Wxh[(size_t)gn * C + c8]) =
                *reinterpret_cast<const uint4*>(&S[n * B_PITCH + c8]);
    }
}

// ---------------- kernel 2: edge scatter (4 edges per 16-lane group) ---------
__global__ __launch_bounds__(256) void scatter_kernel(const int* __restrict__ edges)
{
    const int gidx = blockIdx.x * 16 + (threadIdx.x >> 4);   // quad index
    const int l    = threadIdx.x & 15;

    const int4 ea = reinterpret_cast<const int4*>(edges)[gidx * 2];
    const int4 eb = reinterpret_cast<const int4*>(edges)[gidx * 2 + 1];

    const int tgt[4] = {ea.x, ea.z, eb.x, eb.z};
    const int src[4] = {ea.y, ea.w, eb.y, eb.w};

    float ex[4];
#pragma unroll
    for (int q = 0; q < 4; q++) ex[q] = __ldg(&g_expa[src[q]]);

    uint4 h[4];
#pragma unroll
    for (int q = 0; q < 4; q++)
        h[q] = *reinterpret_cast<const uint4*>(&g_Wxh[(size_t)src[q] * C + l * 8]);

#pragma unroll
    for (int q = 0; q < 4; q++) {
        const unsigned hv[4] = {h[q].x, h[q].y, h[q].z, h[q].w};
        unsigned p[4];
#pragma unroll
        for (int i = 0; i < 4; i++) {
            float2 f = __half22float2(*reinterpret_cast<const __half2*>(&hv[i]));
            __half2 r = __floats2half2_rn(f.x * ex[q], f.y * ex[q]);
            p[i] = *reinterpret_cast<unsigned*>(&r);
        }
        __half* np = &g_numh[(size_t)tgt[q] * C + l * 8];
        asm volatile("red.global.add.noftz.v4.f16x2 [%0], {%1, %2, %3, %4};"
                     :: "l"(np), "r"(p[0]), "r"(p[1]), "r"(p[2]), "r"(p[3])
                     : "memory");
    }

    if (l == 0) {
#pragma unroll
        for (int q = 0; q < 4; q++)
            atomicAdd(&g_den[tgt[q]], ex[q]);
    }
}

// ---------------- kernel 3: normalize + transpose, 32 n x 128 o per block ----
__global__ __launch_bounds__(256) void finalize_kernel(float* __restrict__ out)
{
    __shared__ float tile[32][129];
    __shared__ float dsh[32];

    const int tid  = threadIdx.x;
    const int lane = tid & 31;
    const int w    = tid >> 5;
    const int n0   = blockIdx.x * 32;

    if (tid < 32) {
        float d = g_den[n0 + tid];
        dsh[tid] = (d == 0.f) ? 1.f : d;
    }

#pragma unroll
    for (int it = 0; it < 2; it++) {
        const int idx = it * 256 + tid;
        const int n   = idx >> 4;
        const int o8  = (idx & 15) * 8;
        const uint4 hv =
            *reinterpret_cast<const uint4*>(&g_numh[(size_t)(n0 + n) * C + o8]);
        const unsigned hs[4] = {hv.x, hv.y, hv.z, hv.w};
#pragma unroll
        for (int i = 0; i < 4; i++) {
            const float2 f = __half22float2(*reinterpret_cast<const __half2*>(&hs[i]));
            tile[n][o8 + i * 2 + 0] = f.x;
            tile[n][o8 + i * 2 + 1] = f.y;
        }
    }
    __syncthreads();

    const float rd = 1.f / dsh[lane];
#pragma unroll
    for (int r = 0; r < 16; r++) {
        const int o = w + r * 8;
        out[(size_t)o * N_OUT + n0 + lane] = tile[lane][o] * rd;
    }
}

// ---------------- launch ------------------------------------------------------
extern "C" void kernel_launch(void* const* d_in, const int* in_sizes, int n_in,
                              void* d_out, int out_size)
{
    const float* x     = (const float*)d_in[0];
    const int*   edges = (const int*)  d_in[1];
    const float* W     = (const float*)d_in[2];
    const float* b     = (const float*)d_in[3];
    const float* att   = (const float*)d_in[4];
    const float* alpha = (const float*)d_in[5];
    float* out = (float*)d_out;

    wcvt_kernel<<<64, 256>>>(W);
    gemm_kernel<<<GEMM_BLOCKS, 256>>>(x, b, att, alpha);
    scatter_kernel<<<N_EDGES / 64, 256>>>(edges);
    finalize_kernel<<<N_OUT / 32, 256>>>(out);
}